// round 6
// baseline (speedup 1.0000x reference)
#include <cuda_runtime.h>
#include <cuda_bf16.h>
#include <cstdint>

// DifferentiableNLMS: B=32, T=2000, F=513, L=32, mu=0.1, eps=1e-8
// Two threads per (b,f) sequence: thread h owns taps [16h, 16h+16) and runs
// on a time-shifted x stream (h=0 shifted by -16 frames; zero-pad makes this
// exact), so both threads execute identical code on an 8-pair (16-sample)
// ring with compile-time indices. Partial dots/norms/cross-correlations are
// summed with one lane-xor shuffle. Two-step lookahead + packed f32x2 FMAs.

#define NB 32
#define NT 2000
#define NF 513
#define NL 32
#define MU 0.1f
#define EPSV 1e-8f

#define NPAIR (NB * NF)        // 16416 sequences
#define NTHREAD (NPAIR * 2)    // 32832 threads = 1026 full warps
#define NSTEP 16               // steps per block (= one full ring revolution)
#define NPB 8                  // lookahead-pairs per block
#define NDBL 62                // 62*2+1 = 125 blocks = 2000/16

typedef unsigned long long u64;

__device__ __forceinline__ u64 ffma2(u64 a, u64 b, u64 c) {
    u64 d; asm("fma.rn.f32x2 %0, %1, %2, %3;" : "=l"(d) : "l"(a), "l"(b), "l"(c));
    return d;
}
__device__ __forceinline__ u64 fadd2(u64 a, u64 b) {
    u64 d; asm("add.rn.f32x2 %0, %1, %2;" : "=l"(d) : "l"(a), "l"(b));
    return d;
}
__device__ __forceinline__ u64 pack2(float lo, float hi) {
    u64 d; asm("mov.b64 %0, {%1, %2};" : "=l"(d) : "f"(lo), "f"(hi));
    return d;
}
__device__ __forceinline__ void unpack2(u64 v, float& lo, float& hi) {
    asm("mov.b64 {%0, %1}, %2;" : "=f"(lo), "=f"(hi) : "l"(v));
}
__device__ __forceinline__ u64 shfl64(u64 v) {
    return __shfl_xor_sync(0xFFFFFFFFu, v, 1);
}

// Guarded prefetch (first block only: h=0's shifted indices go negative -> 0).
__device__ __forceinline__ void prefetch_g(float (&x)[NSTEP], float (&y)[NSTEP],
                                           const float* __restrict__ xp,
                                           const float* __restrict__ yp,
                                           int t, int off)
{
#pragma unroll
    for (int u = 0; u < NSTEP; u++) {
        int ti = t + u - off;
        x[u] = (ti >= 0) ? __ldg(xp + (size_t)ti * NF) : 0.f;
        y[u] = __ldg(yp + (size_t)(t + u) * NF);
    }
}
// Unguarded prefetch (t >= 16 -> shifted index always in range).
__device__ __forceinline__ void prefetch_u(float (&x)[NSTEP], float (&y)[NSTEP],
                                           const float* __restrict__ xp,
                                           const float* __restrict__ yp,
                                           int t, int off)
{
#pragma unroll
    for (int u = 0; u < NSTEP; u++) {
        x[u] = __ldg(xp + (size_t)(t + u - off) * NF);
        y[u] = __ldg(yp + (size_t)(t + u) * NF);
    }
}

__device__ __forceinline__ void run_block(
    u64 (&W2)[8], u64 (&P)[8], u64 (&Q)[8],
    float& S, float& CC, float& xlast,
    const float (&xb)[NSTEP], const float (&yb)[NSTEP],
    float* __restrict__ ep, int t0, int h)
{
    float minv[NSTEP];
    float ccs[NPB];
    float xm1_0 = xlast;

    // ---- Prologue: local partial norms / cross-correlations (X-only) ----
    // Reads OLD ring slots (drops) before insertion; independent of W, so
    // the shuffles and MUFU.RCPs sit off the serial recursion path.
    u64 spp[NPB];
    float cpl[NPB];
    {
        float Sl = S, CCl = CC;
#pragma unroll
        for (int p = 0; p < NPB; p++) {
            float a, b, bq, cq;
            unpack2(P[p], a, b);   // (x'_{t-17}, x'_{t-16})
            unpack2(Q[p], bq, cq); // (x'_{t-16}, x'_{t-15})
            float xm1 = p ? xb[2 * p - 1] : xm1_0;
            float x0 = xb[2 * p], x1 = xb[2 * p + 1];
            Sl = fmaf(x0, x0, Sl);
            Sl = fmaf(-b, b, Sl);
            float s0 = Sl;
            Sl = fmaf(x1, x1, Sl);
            Sl = fmaf(-cq, cq, Sl);
            spp[p] = pack2(s0, Sl);
            CCl = fmaf(xm1, x0, CCl);
            CCl = fmaf(x0, x1, CCl);
            CCl = fmaf(-a, b, CCl);
            CCl = fmaf(-bq, cq, CCl);
            cpl[p] = CCl;
        }
        S = Sl; CC = CCl;
    }
    // Exchange partial norms, compute step sizes (both threads redundantly).
#pragma unroll
    for (int p = 0; p < NPB; p++) {
        u64 ss = fadd2(spp[p], shfl64(spp[p]));
        float s0, s1;
        unpack2(ss, s0, s1);
        minv[2 * p]     = __fdividef(MU, s0 + EPSV);
        minv[2 * p + 1] = __fdividef(MU, s1 + EPSV);
    }
    // Exchange partial cross-correlations.
#pragma unroll
    for (int p = 0; p < NPB; p += 2) {
        u64 cv = pack2(cpl[p], cpl[p + 1]);
        u64 cs = fadd2(cv, shfl64(cv));
        unpack2(cs, ccs[p], ccs[p + 1]);
    }
    xlast = xb[NSTEP - 1];

    // ---- Serial recursion: 2 steps per iteration ----
#pragma unroll
    for (int p = 0; p < NPB; p++) {
        float xm1 = p ? xb[2 * p - 1] : xm1_0;
        float x0 = xb[2 * p], x1 = xb[2 * p + 1];
        P[p] = pack2(xm1, x0);  // slot holds (x'_{t-1}, x'_t)
        Q[p] = pack2(x0, x1);   // slot holds (x'_t, x'_{t+1})

        // Half-dots over own 8 pair-slots: window pair i -> slot (p+1+i)&7.
        u64 a0 = 0, a1 = 0, a2 = 0, a3 = 0;
        u64 b0 = 0, b1 = 0, b2 = 0, b3 = 0;
#pragma unroll
        for (int i = 0; i < 8; i += 4) {
            a0 = ffma2(W2[i + 0], P[(p + 1 + i) & 7], a0);
            a1 = ffma2(W2[i + 1], P[(p + 2 + i) & 7], a1);
            a2 = ffma2(W2[i + 2], P[(p + 3 + i) & 7], a2);
            a3 = ffma2(W2[i + 3], P[(p + 4 + i) & 7], a3);
            b0 = ffma2(W2[i + 0], Q[(p + 1 + i) & 7], b0);
            b1 = ffma2(W2[i + 1], Q[(p + 2 + i) & 7], b1);
            b2 = ffma2(W2[i + 2], Q[(p + 3 + i) & 7], b2);
            b3 = ffma2(W2[i + 3], Q[(p + 4 + i) & 7], b3);
        }
        u64 ap = fadd2(fadd2(a0, a1), fadd2(a2, a3));
        u64 aq = fadd2(fadd2(b0, b1), fadd2(b2, b3));
        float plo, phi, qlo, qhi;
        unpack2(ap, plo, phi);
        unpack2(aq, qlo, qhi);
        // Sum halves across the lane pair with one 64-bit butterfly.
        u64 pq = pack2(plo + phi, qlo + qhi);
        u64 pqs = fadd2(pq, shfl64(pq));
        float pt, qt;
        unpack2(pqs, pt, qt);

        float e0 = yb[2 * p] - pt;
        float c0 = e0 * minv[2 * p];
        float e1 = fmaf(-c0, ccs[p], yb[2 * p + 1] - qt);
        float c1 = e1 * minv[2 * p + 1];

        if (h) {  // one writer per sequence
            ep[(size_t)(t0 + 2 * p) * NF] = e0;
            ep[(size_t)(t0 + 2 * p + 1) * NF] = e1;
        }

        u64 c0p = pack2(c0, c0);
        u64 c1p = pack2(c1, c1);
#pragma unroll
        for (int i = 0; i < 8; i++) {
            W2[i] = ffma2(c1p, Q[(p + 1 + i) & 7],
                          ffma2(c0p, P[(p + 1 + i) & 7], W2[i]));
        }
    }
}

__global__ void __launch_bounds__(128, 2)
nlms_kernel(const float* __restrict__ X, const float* __restrict__ Y,
            const float* __restrict__ Wp, float* __restrict__ out,
            int write_w)
{
    int gtid = blockIdx.x * blockDim.x + threadIdx.x;
    if (gtid >= NTHREAD) return;
    int h = gtid & 1;          // tap-half owner
    int seq = gtid >> 1;
    int b = seq / NF;
    int f = seq - b * NF;
    int off = 16 * (1 - h);    // time shift of this thread's x stream

    size_t base = (size_t)b * NT * NF + f;
    const float* xp = X + base;
    const float* yp = Y + base;
    float* ep = out + base;    // E_hat_mag at offset 0

    u64 W2[8], P[8], Q[8];
#pragma unroll
    for (int i = 0; i < 8; i++) {
        int j = 16 * h + 2 * i;
        float w0 = Wp[((size_t)b * NL + j) * NF + f];
        float w1 = Wp[((size_t)b * NL + j + 1) * NF + f];
        W2[i] = pack2(w0, w1);
        P[i] = 0;  // zero pad: window starts empty
        Q[i] = 0;
    }
    float S = 0.f, CC = 0.f, xlast = 0.f;

    float xA[NSTEP], yA[NSTEP], xB[NSTEP], yB[NSTEP];
    prefetch_g(xA, yA, xp, yp, 0, off);

    int t0 = 0;
    for (int bb = 0; bb < NDBL; bb++) {
        prefetch_u(xB, yB, xp, yp, t0 + NSTEP, off);
        run_block(W2, P, Q, S, CC, xlast, xA, yA, ep, t0, h);
        t0 += NSTEP;
        prefetch_u(xA, yA, xp, yp, t0 + NSTEP, off);  // last lands on block 124
        run_block(W2, P, Q, S, CC, xlast, xB, yB, ep, t0, h);
        t0 += NSTEP;
    }
    run_block(W2, P, Q, S, CC, xlast, xA, yA, ep, t0, h);  // t0 = 1984

    if (write_w) {
        float* wf = out + (size_t)NB * NT * NF;  // W_final after E
#pragma unroll
        for (int i = 0; i < 8; i++) {
            int j = 16 * h + 2 * i;
            float w0, w1;
            unpack2(W2[i], w0, w1);
            wf[((size_t)b * NL + j) * NF + f] = w0;
            wf[((size_t)b * NL + j + 1) * NF + f] = w1;
        }
    }
}

extern "C" void kernel_launch(void* const* d_in, const int* in_sizes, int n_in,
                              void* d_out, int out_size)
{
    const float* X  = (const float*)d_in[0];  // X_hat_mag [B,T,F]
    const float* Y  = (const float*)d_in[1];  // Y_mag     [B,T,F]
    const float* Wp = (const float*)d_in[2];  // W_prev    [B,L,F]
    float* out = (float*)d_out;

    long long need = (long long)NB * NT * NF + (long long)NB * NL * NF;
    int write_w = ((long long)out_size >= need) ? 1 : 0;

    // 32832 threads (1026 full warps), 128/block -> 257 blocks, one wave.
    nlms_kernel<<<257, 128>>>(X, Y, Wp, out, write_w);
}